// round 13
// baseline (speedup 1.0000x reference)
#include <cuda_runtime.h>
#include <cuda_bf16.h>
#include <math.h>
#include <math_constants.h>
#include <cstdint>

#define T_LEN 2048

// ---------------- scratch (no allocations allowed) ----------------
__device__ float g_h [4096 * 512];
__device__ float g_t1[4096 * 512];
__device__ float g_t2[4096 * 512];
__device__ float g_t3[4096 * 512];
__device__ float g_rope[2048 * 16 * 2];
__device__ __nv_bfloat16 g_A0h[4096 * 512], g_A0l[4096 * 512];
__device__ __nv_bfloat16 g_A1h[4096 * 512], g_A1l[4096 * 512];
__device__ __nv_bfloat16 g_Qh[4096 * 256], g_Ql[4096 * 256];
__device__ __nv_bfloat16 g_Kh[4096 * 256], g_Kl[4096 * 256];
__device__ __nv_bfloat16 g_Vh[4096 * 512], g_Vl[4096 * 512];
// weight rows: [0:1024) qkv | [1024:1536) wproj | [1536:2048) ew0 | [2048:2560) ew1 | [2560:3072) ew2 | [3072:3104) ewout
__device__ __nv_bfloat16 g_Wh[3104 * 512], g_Wl[3104 * 512];

// ---------------- helpers ----------------
static __device__ __forceinline__ uint32_t smem_u32(const void* p) {
    uint32_t a;
    asm("{ .reg .u64 t; cvta.to.shared.u64 t, %1; cvt.u32.u64 %0, t; }" : "=r"(a) : "l"(p));
    return a;
}
static __device__ __forceinline__ void hilo(float v, __nv_bfloat16& h, __nv_bfloat16& l) {
    h = __float2bfloat16(v);
    l = __float2bfloat16(v - __bfloat162float(h));
}
static __device__ __forceinline__ void packhl(float a, float b, uint32_t& ph, uint32_t& pl) {
    __nv_bfloat162 hp, lp;
    hp.x = __float2bfloat16(a);
    hp.y = __float2bfloat16(b);
    lp.x = __float2bfloat16(a - __bfloat162float(hp.x));
    lp.y = __float2bfloat16(b - __bfloat162float(hp.y));
    ph = *(uint32_t*)&hp;
    pl = *(uint32_t*)&lp;
}

#define LDSM_X4(r, a)                                                          \
    asm volatile("ldmatrix.sync.aligned.m8n8.x4.shared.b16 {%0,%1,%2,%3}, [%4];" \
        : "=r"((r)[0]), "=r"((r)[1]), "=r"((r)[2]), "=r"((r)[3]) : "r"(a))
#define LDSM_X2(r, a)                                                          \
    asm volatile("ldmatrix.sync.aligned.m8n8.x2.shared.b16 {%0,%1}, [%2];"     \
        : "=r"((r)[0]), "=r"((r)[1]) : "r"(a))
#define LDSM_X4_T(r, a)                                                        \
    asm volatile("ldmatrix.sync.aligned.m8n8.x4.trans.shared.b16 {%0,%1,%2,%3}, [%4];" \
        : "=r"((r)[0]), "=r"((r)[1]), "=r"((r)[2]), "=r"((r)[3]) : "r"(a))
#define MMA_BF16(d, A, B)                                                      \
    asm volatile("mma.sync.aligned.m16n8k16.row.col.f32.bf16.bf16.f32 "        \
        "{%0,%1,%2,%3}, {%4,%5,%6,%7}, {%8,%9}, {%0,%1,%2,%3};"                \
        : "+f"((d)[0]), "+f"((d)[1]), "+f"((d)[2]), "+f"((d)[3])               \
        : "r"((A)[0]), "r"((A)[1]), "r"((A)[2]), "r"((A)[3]),                  \
          "r"((B)[0]), "r"((B)[1]))
#define CPA(dst, src, sz) \
    asm volatile("cp.async.ca.shared.global [%0], [%1], 16, %2;" :: "r"(dst), "l"(src), "r"(sz))
#define CP_COMMIT asm volatile("cp.async.commit_group;" ::: "memory")
#define CP_WAIT0  asm volatile("cp.async.wait_group 0;" ::: "memory")
#define CP_WAIT1  asm volatile("cp.async.wait_group 1;" ::: "memory")

// ---------------- fused prep: weights hilo + x hilo + rope table ----------------
__global__ void prep_kernel(
    const float* __restrict__ x, const float* __restrict__ qp, const float* __restrict__ kp,
    const float* __restrict__ wv, const float* __restrict__ wproj,
    const float* __restrict__ ew0, const float* __restrict__ ew1,
    const float* __restrict__ ew2, const float* __restrict__ ewout,
    __nv_bfloat16* __restrict__ Wh, __nv_bfloat16* __restrict__ Wl,
    __nv_bfloat16* __restrict__ A0h, __nv_bfloat16* __restrict__ A0l,
    float* __restrict__ rope)
{
    int idx = blockIdx.x * blockDim.x + threadIdx.x;
    if (idx < 524288) {
        int n = idx >> 9, d = idx & 511;
        float v;
        if (n < 256) v = qp[((n >> 5) * 512 + d) * 32 + (n & 31)];
        else if (n < 512) { int nn = n - 256; v = kp[((nn >> 5) * 512 + d) * 32 + (nn & 31)]; }
        else v = wv[(size_t)(n - 512) * 512 + d];
        hilo(v, Wh[idx], Wl[idx]);
    } else if (idx < 786432) {
        int i = idx - 524288;
        hilo(wproj[i], Wh[1024 * 512 + i], Wl[1024 * 512 + i]);
    } else if (idx < 1048576) {
        int i = idx - 786432;
        hilo(ew0[i], Wh[1536 * 512 + i], Wl[1536 * 512 + i]);
    } else if (idx < 1310720) {
        int i = idx - 1048576;
        hilo(ew1[i], Wh[2048 * 512 + i], Wl[2048 * 512 + i]);
    } else if (idx < 1572864) {
        int i = idx - 1310720;
        hilo(ew2[i], Wh[2560 * 512 + i], Wl[2560 * 512 + i]);
    } else if (idx < 1589248) {
        int i = idx - 1572864;
        hilo(ewout[i], Wh[3072 * 512 + i], Wl[3072 * 512 + i]);
    } else if (idx < 3686400) {
        int i = idx - 1589248;
        hilo(x[i], A0h[i], A0l[i]);
    } else if (idx < 3719168) {
        int i2 = idx - 3686400;       // t*16 + i
        int t = i2 >> 4, i = i2 & 15;
        double fd = pow(10000.0, -(double)(2 * i) / 32.0);
        float ang = (float)t * (float)fd;
        double ad = (double)ang;
        rope[i2 * 2]     = (float)cos(ad);
        rope[i2 * 2 + 1] = (float)sin(ad);
    }
}

// ---------------- HMMA bf16x3 GEMM, tile 128x128, term-major MMA ordering ----------------
// D[m][n] = sum_k A[m][k]*B[n][k], K=512, 8 warps as 2m x 4n (warp tile 64x32).
// EPI: 0 none, 1 res+acc, 2 res+silu(acc), 3 tanh(acc/(softplus(extra[n])+1e-4))
// OMODE: 0 none, 1 full hilo out, 2 QKV fused epilogue (rope for n<512, V hilo for n>=512)
#define PAD 72
#define ARR (128 * PAD)
#define STAGEB (4 * ARR * 2)
#define GEMM_SMEM (2 * STAGEB)
template <int EPI, int OMODE>
__global__ void __launch_bounds__(256, 1) mma_gemm(
    const __nv_bfloat16* __restrict__ Ah, const __nv_bfloat16* __restrict__ Al,
    const __nv_bfloat16* __restrict__ Bh, const __nv_bfloat16* __restrict__ Bl,
    const float* __restrict__ Res, float* __restrict__ C,
    int Ntot, int NtotB, const float* __restrict__ extra,
    __nv_bfloat16* __restrict__ Oh, __nv_bfloat16* __restrict__ Ol,
    __nv_bfloat16* __restrict__ Qh, __nv_bfloat16* __restrict__ Ql,
    __nv_bfloat16* __restrict__ Kh, __nv_bfloat16* __restrict__ Kl,
    const float* __restrict__ rope_tab, const float* __restrict__ qgain)
{
    extern __shared__ __nv_bfloat16 smb[];
    uint32_t sbase = smem_u32(smb);

    int tid = threadIdx.x, lane = tid & 31, wid = tid >> 5;
    int warp_m = wid & 1, warp_n = wid >> 1;
    int m0 = blockIdx.y * 128, n0 = blockIdx.x * 128;

    uint32_t a_row = warp_m * 64 + (lane & 15);
    uint32_t a_ko  = (lane >> 4) * 8;
    uint32_t b_row = warp_n * 32 + (lane & 7);
    uint32_t b_ko  = ((lane >> 3) & 1) * 8;

    float acc[4][4][4] = {};

    auto issue = [&](int c) {
        uint32_t st = (uint32_t)(c & 1) * STAGEB;
        int k0c = c * 64;
#pragma unroll
        for (int t = 0; t < 4; t++) {
            int idx = tid + t * 256;
            int r = idx >> 3, q = idx & 7;
            uint32_t so = st + (uint32_t)(r * PAD + q * 8) * 2;
            size_t g = (size_t)(m0 + r) * 512 + k0c + q * 8;
            CPA(sbase + so,            Ah + g, 16);
            CPA(sbase + so + ARR * 2,  Al + g, 16);
        }
#pragma unroll
        for (int t = 0; t < 4; t++) {
            int idx = tid + t * 256;
            int r = idx >> 3, q = idx & 7;
            uint32_t so = st + (uint32_t)(2 * ARR + r * PAD + q * 8) * 2;
            int n = n0 + r;
            int ok = (n < NtotB) ? 16 : 0;
            size_t g = (size_t)(ok ? n : 0) * 512 + k0c + q * 8;
            CPA(sbase + so,            Bh + g, ok);
            CPA(sbase + so + ARR * 2,  Bl + g, ok);
        }
        CP_COMMIT;
    };

    issue(0);
    for (int c = 0; c < 8; c++) {
        CP_WAIT0;
        __syncthreads();
        if (c < 7) issue(c + 1);

        uint32_t st = (uint32_t)(c & 1) * STAGEB;
        uint32_t uAh = sbase + st;
        uint32_t uAl = uAh + ARR * 2;
        uint32_t uBh = uAl + ARR * 2;
        uint32_t uBl = uBh + ARR * 2;

#pragma unroll
        for (int kk = 0; kk < 4; kk++) {
            // load ALL fragments first
            uint32_t bh[4][2], bl[4][2];
#pragma unroll
            for (int ni = 0; ni < 4; ni++) {
                uint32_t off = ((b_row + ni * 8) * PAD + kk * 16 + b_ko) * 2;
                LDSM_X2(bh[ni], uBh + off);
                LDSM_X2(bl[ni], uBl + off);
            }
            uint32_t ah[4][4], al[4][4];
#pragma unroll
            for (int mi = 0; mi < 4; mi++) {
                uint32_t off = ((a_row + mi * 16) * PAD + kk * 16 + a_ko) * 2;
                LDSM_X4(ah[mi], uAh + off);
                LDSM_X4(al[mi], uAl + off);
            }
            // term-major: consecutive MMAs hit different accumulators (dep distance 16)
#pragma unroll
            for (int mi = 0; mi < 4; mi++)
#pragma unroll
                for (int ni = 0; ni < 4; ni++)
                    MMA_BF16(acc[mi][ni], ah[mi], bh[ni]);
#pragma unroll
            for (int mi = 0; mi < 4; mi++)
#pragma unroll
                for (int ni = 0; ni < 4; ni++)
                    MMA_BF16(acc[mi][ni], ah[mi], bl[ni]);
#pragma unroll
            for (int mi = 0; mi < 4; mi++)
#pragma unroll
                for (int ni = 0; ni < 4; ni++)
                    MMA_BF16(acc[mi][ni], al[mi], bh[ni]);
        }
        __syncthreads();
    }

    // epilogue
    int gid = lane >> 2, tig = lane & 3;

    if (OMODE == 2) {
        int colbase = n0 + warp_n * 32;   // warp-uniform, one 32-col head group
        if (colbase < 512) {
            // q/k region: rope rotate in-register, pairs (ni, ni+2)
            int which = colbase >= 256;
            int hh = (colbase >> 5) & 7;
            float scale = which ? 1.0f : (qgain[hh] * 0.17677669529663687f);
            __nv_bfloat16* dh = which ? Kh : Qh;
            __nv_bfloat16* dl = which ? Kl : Ql;
            int off0 = colbase & 255;
#pragma unroll
            for (int mi = 0; mi < 4; mi++) {
#pragma unroll
                for (int half = 0; half < 2; half++) {
                    int m = m0 + warp_m * 64 + mi * 16 + gid + half * 8;
                    int t = m & (T_LEN - 1);
#pragma unroll
                    for (int ni = 0; ni < 2; ni++) {
#pragma unroll
                        for (int e = 0; e < 2; e++) {
                            int i = ni * 8 + tig * 2 + e;
                            float x1 = acc[mi][ni][half * 2 + e];
                            float x2 = acc[mi][ni + 2][half * 2 + e];
                            float cth = rope_tab[(t * 16 + i) * 2];
                            float sth = rope_tab[(t * 16 + i) * 2 + 1];
                            float o1 = (x1 * cth - x2 * sth) * scale;
                            float o2 = (x2 * cth + x1 * sth) * scale;
                            __nv_bfloat16 h1, l1, h2, l2;
                            hilo(o1, h1, l1); hilo(o2, h2, l2);
                            size_t base = (size_t)m * 256 + off0 + i;
                            dh[base] = h1;      dl[base] = l1;
                            dh[base + 16] = h2; dl[base + 16] = l2;
                        }
                    }
                }
            }
        } else {
            // V region: hilo split
#pragma unroll
            for (int mi = 0; mi < 4; mi++) {
#pragma unroll
                for (int ni = 0; ni < 4; ni++) {
#pragma unroll
                    for (int half = 0; half < 2; half++) {
                        int m = m0 + warp_m * 64 + mi * 16 + gid + half * 8;
                        int nb = colbase + ni * 8 + tig * 2;
#pragma unroll
                        for (int e = 0; e < 2; e++) {
                            int n = nb + e;
                            __nv_bfloat16 hx, lx;
                            hilo(acc[mi][ni][half * 2 + e], hx, lx);
                            Oh[(size_t)m * 512 + (n - 512)] = hx;
                            Ol[(size_t)m * 512 + (n - 512)] = lx;
                        }
                    }
                }
            }
        }
        return;
    }

#pragma unroll
    for (int mi = 0; mi < 4; mi++) {
#pragma unroll
        for (int ni = 0; ni < 4; ni++) {
#pragma unroll
            for (int half = 0; half < 2; half++) {
                int m = m0 + warp_m * 64 + mi * 16 + gid + half * 8;
                int nbase = n0 + warp_n * 32 + ni * 8 + tig * 2;
#pragma unroll
                for (int e = 0; e < 2; e++) {
                    int n = nbase + e;
                    if (n >= Ntot) continue;
                    float v = acc[mi][ni][half * 2 + e];
                    if (EPI == 1) {
                        v += Res[(size_t)m * Ntot + n];
                    } else if (EPI == 2) {
                        float sg = 1.0f / (1.0f + __expf(-v));
                        v = Res[(size_t)m * Ntot + n] + v * sg;
                    } else if (EPI == 3) {
                        float ct = extra[n];
                        float sp = (ct > 20.0f) ? ct : log1pf(__expf(ct));
                        v = tanhf(v / (sp + 1e-4f));
                    }
                    C[(size_t)m * Ntot + n] = v;
                    if (OMODE == 1) {
                        __nv_bfloat16 hx, lx;
                        hilo(v, hx, lx);
                        Oh[(size_t)m * 512 + n] = hx;
                        Ol[(size_t)m * 512 + n] = lx;
                    }
                }
            }
        }
    }
}

// ---------------- HMMA flash attention + self-align, bf16x3, cp.async double-buffered ----------------
// BQ=128 (8 warps), K tiles of 64, 2-stage K/V pipeline. grid (16, 8, 2), 256 thr.
#define AQ_E   (128 * 40)
#define AK_E   (64 * 40)
#define AV_E   (64 * 72)
#define ASTAGE (2 * AK_E + 2 * AV_E)
#define ATTN_SMEM ((2 * AQ_E + 2 * ASTAGE) * 2)   // 77824 bytes
__global__ void __launch_bounds__(256, 2) attn_mma(
    const __nv_bfloat16* __restrict__ Qh_, const __nv_bfloat16* __restrict__ Ql_,
    const __nv_bfloat16* __restrict__ Kh_, const __nv_bfloat16* __restrict__ Kl_,
    const __nv_bfloat16* __restrict__ Vh_, const __nv_bfloat16* __restrict__ Vl_,
    __nv_bfloat16* __restrict__ yh, __nv_bfloat16* __restrict__ yl)
{
    extern __shared__ __nv_bfloat16 sb[];
    __nv_bfloat16* sQh = sb;
    __nv_bfloat16* sQl = sQh + AQ_E;
    __nv_bfloat16* stage0 = sQl + AQ_E;

    int qb = (int)gridDim.x - 1 - (int)blockIdx.x;
    int h = blockIdx.y, b = blockIdx.z;
    int tid = threadIdx.x, lane = tid & 31, w = tid >> 5;
    int q0 = qb * 128;
    int rw = q0 + w * 16;
    const size_t hb = (size_t)b * T_LEN;
    int ntiles = 2 * qb + 2;

    auto issueKV = [&](int j) {
        int k0 = j * 64;
        uint32_t st = smem_u32(stage0 + (j & 1) * ASTAGE);
        {
            int r = tid >> 2, seg = tid & 3;
            size_t g = (hb + k0 + r) * 256 + h * 32 + seg * 8;
            uint32_t d = st + (uint32_t)(r * 40 + seg * 8) * 2;
            CPA(d,              Kh_ + g, 16);
            CPA(d + AK_E * 2,   Kl_ + g, 16);
        }
#pragma unroll
        for (int t2 = 0; t2 < 2; t2++) {
            int idx = tid + t2 * 256;
            int r = idx >> 3, seg = idx & 7;
            size_t g = (hb + k0 + r) * 512 + h * 64 + seg * 8;
            uint32_t d = st + (uint32_t)(2 * AK_E + r * 72 + seg * 8) * 2;
            CPA(d,              Vh_ + g, 16);
            CPA(d + AV_E * 2,   Vl_ + g, 16);
        }
        CP_COMMIT;
    };

    issueKV(0);

    for (int i = tid; i < 512; i += 256) {
        int r = i >> 2, seg = i & 3;
        size_t g = (hb + q0 + r) * 256 + h * 32 + seg * 8;
        *(float4*)(sQh + r * 40 + seg * 8) = *(const float4*)(Qh_ + g);
        *(float4*)(sQl + r * 40 + seg * 8) = *(const float4*)(Ql_ + g);
    }
    __syncthreads();

    uint32_t qfh[2][4], qfl[2][4];
    {
        int mrow = (lane & 7) + 8 * ((lane >> 3) & 1);
        int koff = 8 * (lane >> 4);
#pragma unroll
        for (int kj = 0; kj < 2; kj++) {
            LDSM_X4(qfh[kj], smem_u32(sQh + (w * 16 + mrow) * 40 + kj * 16 + koff));
            LDSM_X4(qfl[kj], smem_u32(sQl + (w * 16 + mrow) * 40 + kj * 16 + koff));
        }
    }

    float m_[2] = {-1e30f, -1e30f}, l_[2] = {0.f, 0.f};
    float o[8][4] = {};

    for (int j = 0; j < ntiles; j++) {
        if (j > 0) __syncthreads();
        if (j + 1 < ntiles) { issueKV(j + 1); CP_WAIT1; }
        else                { CP_WAIT0; }
        __syncthreads();

        __nv_bfloat16* sKh = stage0 + (j & 1) * ASTAGE;
        __nv_bfloat16* sKl = sKh + AK_E;
        __nv_bfloat16* sVh = sKl + AK_E;
        __nv_bfloat16* sVl = sVh + AV_E;
        int k0 = j * 64;

        float s[8][4] = {};
        {
            int nrow = (lane & 7) + 8 * (lane >> 4);
            int koff = 8 * ((lane >> 3) & 1);
#pragma unroll
            for (int kj = 0; kj < 2; kj++) {
#pragma unroll
                for (int p = 0; p < 4; p++) {
                    uint32_t kb_h[4], kb_l[4];
                    LDSM_X4(kb_h, smem_u32(sKh + (p * 16 + nrow) * 40 + kj * 16 + koff));
                    LDSM_X4(kb_l, smem_u32(sKl + (p * 16 + nrow) * 40 + kj * 16 + koff));
                    // interleave n-halves: dep distance 2 per accumulator
                    MMA_BF16(s[2 * p],     qfh[kj], kb_h);
                    MMA_BF16(s[2 * p + 1], qfh[kj], kb_h + 2);
                    MMA_BF16(s[2 * p],     qfh[kj], kb_l);
                    MMA_BF16(s[2 * p + 1], qfh[kj], kb_l + 2);
                    MMA_BF16(s[2 * p],     qfl[kj], kb_h);
                    MMA_BF16(s[2 * p + 1], qfl[kj], kb_h + 2);
                }
            }
        }

        if (k0 + 63 > rw) {
#pragma unroll
            for (int nt = 0; nt < 8; nt++)
#pragma unroll
                for (int e = 0; e < 4; e++) {
                    int col = k0 + nt * 8 + (lane & 3) * 2 + (e & 1);
                    int row = rw + (lane >> 2) + (e >> 1) * 8;
                    if (col > row) s[nt][e] = -1e30f;
                }
        }

        float alpha[2];
#pragma unroll
        for (int half = 0; half < 2; half++) {
            float mx = -1e30f;
#pragma unroll
            for (int nt = 0; nt < 8; nt++)
                mx = fmaxf(mx, fmaxf(s[nt][2 * half], s[nt][2 * half + 1]));
            mx = fmaxf(mx, __shfl_xor_sync(0xffffffffu, mx, 1));
            mx = fmaxf(mx, __shfl_xor_sync(0xffffffffu, mx, 2));
            float mnew = fmaxf(m_[half], mx);
            alpha[half] = __expf(m_[half] - mnew);
            m_[half] = mnew;
            float sum = 0.f;
#pragma unroll
            for (int nt = 0; nt < 8; nt++) {
                s[nt][2 * half]     = __expf(s[nt][2 * half] - mnew);
                s[nt][2 * half + 1] = __expf(s[nt][2 * half + 1] - mnew);
                sum += s[nt][2 * half] + s[nt][2 * half + 1];
            }
            sum += __shfl_xor_sync(0xffffffffu, sum, 1);
            sum += __shfl_xor_sync(0xffffffffu, sum, 2);
            l_[half] = l_[half] * alpha[half] + sum;
        }
#pragma unroll
        for (int dt = 0; dt < 8; dt++) {
            o[dt][0] *= alpha[0]; o[dt][1] *= alpha[0];
            o[dt][2] *= alpha[1]; o[dt][3] *= alpha[1];
        }

        uint32_t pah[4][4], pal[4][4];
#pragma unroll
        for (int kj = 0; kj < 4; kj++) {
            packhl(s[2 * kj][0],     s[2 * kj][1],     pah[kj][0], pal[kj][0]);
            packhl(s[2 * kj][2],     s[2 * kj][3],     pah[kj][1], pal[kj][1]);
            packhl(s[2 * kj + 1][0], s[2 * kj + 1][1], pah[kj][2], pal[kj][2]);
            packhl(s[2 * kj + 1][2], s[2 * kj + 1][3], pah[kj][3], pal[kj][3]);
        }

        {
            int vrow = lane & 15;
            int vcol = 8 * (lane >> 4);
#pragma unroll
            for (int kj = 0; kj < 4; kj++) {
#pragma unroll
                for (int p = 0; p < 4; p++) {
                    uint32_t vb_h[4], vb_l[4];
                    LDSM_X4_T(vb_h, smem_u32(sVh + (kj * 16 + vrow) * 72 + p * 16 + vcol));
                    LDSM_X4_T(vb_l, smem_u32(sVl + (kj * 16 + vrow) * 72 + p * 16 + vcol));
                    // interleave n-halves: dep distance 2 per accumulator
                    MMA_BF16(o[2 * p],     pah[kj], vb_h);
                    MMA_BF16(o[2 * p + 1], pah[kj], vb_h + 2);
                    MMA_BF16(o[2 * p],     pah[kj], vb_l);
                    MMA_BF16(o[2 * p + 1], pah[kj], vb_l + 2);
                    MMA_BF16(o[2 * p],     pal[kj], vb_h);
                    MMA_BF16(o[2 * p + 1], pal[kj], vb_h + 2);
                }
            }
        }
    }

#pragma unroll
    for (int half = 0; half < 2; half++) {
        int row = rw + (lane >> 2) + half * 8;
        float dp = 0.f, nn = 0.f;
        float vv[8][2];
#pragma unroll
        for (int dt = 0; dt < 8; dt++) {
            int c0 = dt * 8 + (lane & 3) * 2;
            size_t g = (hb + row) * 512 + h * 64 + c0;
            __nv_bfloat162 th = *(const __nv_bfloat162*)(Vh_ + g);
            __nv_bfloat162 tl = *(const __nv_bfloat162*)(Vl_ + g);
            float v0 = __bfloat162float(th.x) + __bfloat162float(tl.x);
            float v1 = __bfloat162float(th.y) + __bfloat162float(tl.y);
            vv[dt][0] = v0; vv[dt][1] = v1;
            dp += o[dt][2 * half] * v0 + o[dt][2 * half + 1] * v1;
            nn += v0 * v0 + v1 * v1;
        }
        dp += __shfl_xor_sync(0xffffffffu, dp, 1);
        dp += __shfl_xor_sync(0xffffffffu, dp, 2);
        nn += __shfl_xor_sync(0xffffffffu, nn, 1);
        nn += __shfl_xor_sync(0xffffffffu, nn, 2);
        float coef = dp / fmaxf(nn, 1e-24f);
        float linv = 1.0f / l_[half];
#pragma unroll
        for (int dt = 0; dt < 8; dt++) {
            int c0 = dt * 8 + (lane & 3) * 2;
            size_t g = (hb + row) * 512 + h * 64 + c0;
            float y0 = (o[dt][2 * half]     - coef * vv[dt][0]) * linv;
            float y1 = (o[dt][2 * half + 1] - coef * vv[dt][1]) * linv;
            uint32_t ph, pl;
            packhl(y0, y1, ph, pl);
            *(uint32_t*)(yh + g) = ph;
            *(uint32_t*)(yl + g) = pl;
        }
    }
}

// ---------------- layernorm -> bf16 hi/lo ----------------
__global__ void ln_hilo(const float* __restrict__ in, const float* __restrict__ g,
                        const float* __restrict__ bta,
                        __nv_bfloat16* __restrict__ oh, __nv_bfloat16* __restrict__ ol) {
    int row = blockIdx.x * 8 + (threadIdx.x >> 5);
    int lane = threadIdx.x & 31;
    const float* p = in + (size_t)row * 512;
    float v[16];
    float s = 0.f;
#pragma unroll
    for (int j = 0; j < 16; j++) { v[j] = p[lane + 32 * j]; s += v[j]; }
#pragma unroll
    for (int off = 16; off; off >>= 1) s += __shfl_xor_sync(0xffffffffu, s, off);
    float mean = s * (1.0f / 512.0f);
    float s2 = 0.f;
#pragma unroll
    for (int j = 0; j < 16; j++) { float d = v[j] - mean; s2 += d * d; }
#pragma unroll
    for (int off = 16; off; off >>= 1) s2 += __shfl_xor_sync(0xffffffffu, s2, off);
    float r = rsqrtf(s2 * (1.0f / 512.0f) + 1e-5f);
#pragma unroll
    for (int j = 0; j < 16; j++) {
        int c = lane + 32 * j;
        float ov = (v[j] - mean) * r * g[c] + bta[c];
        __nv_bfloat16 hx, lx;
        hilo(ov, hx, lx);
        oh[(size_t)row * 512 + c] = hx;
        ol[(size_t)row * 512 + c] = lx;
    }
}

// ---------------- RMS norm -> bf16 hi/lo ----------------
__global__ void rms_hilo(const float* __restrict__ in,
                         __nv_bfloat16* __restrict__ oh, __nv_bfloat16* __restrict__ ol) {
    int row = blockIdx.x * 8 + (threadIdx.x >> 5);
    int lane = threadIdx.x & 31;
    const float* p = in + (size_t)row * 512;
    float v[16];
    float s2 = 0.f;
#pragma unroll
    for (int j = 0; j < 16; j++) { v[j] = p[lane + 32 * j]; s2 += v[j] * v[j]; }
#pragma unroll
    for (int off = 16; off; off >>= 1) s2 += __shfl_xor_sync(0xffffffffu, s2, off);
    float r = rsqrtf(s2 * (1.0f / 512.0f) + 1e-6f);
#pragma unroll
    for (int j = 0; j < 16; j++) {
        float ov = v[j] * r;
        __nv_bfloat16 hx, lx;
        hilo(ov, hx, lx);
        oh[(size_t)row * 512 + lane + 32 * j] = hx;
        ol[(size_t)row * 512 + lane + 32 * j] = lx;
    }
}

// ---------------- launch ----------------
extern "C" void kernel_launch(void* const* d_in, const int* in_sizes, int n_in,
                              void* d_out, int out_size) {
    const float* x      = (const float*)d_in[0];
    const float* qp     = (const float*)d_in[1];
    const float* kp     = (const float*)d_in[2];
    const float* wv     = (const float*)d_in[3];
    const float* wproj  = (const float*)d_in[4];
    const float* qg     = (const float*)d_in[5];
    const float* ew0    = (const float*)d_in[6];
    const float* g1     = (const float*)d_in[7];
    const float* b1     = (const float*)d_in[8];
    const float* ew1    = (const float*)d_in[9];
    const float* g2     = (const float*)d_in[10];
    const float* b2     = (const float*)d_in[11];
    const float* ew2    = (const float*)d_in[12];
    const float* ewout  = (const float*)d_in[13];
    const float* ctemp  = (const float*)d_in[14];
    float* out = (float*)d_out;

    float *hb, *t1, *t2, *t3, *rope;
    __nv_bfloat16 *A0h, *A0l, *A1h, *A1l, *Wh, *Wl, *Qh, *Ql, *Kh, *Kl, *Vh, *Vl;
    cudaGetSymbolAddress((void**)&hb,  g_h);
    cudaGetSymbolAddress((void**)&t1,  g_t1);
    cudaGetSymbolAddress((void**)&t2,  g_t2);
    cudaGetSymbolAddress((void**)&t3,  g_t3);
    cudaGetSymbolAddress((void**)&rope, g_rope);
    cudaGetSymbolAddress((void**)&A0h, g_A0h);
    cudaGetSymbolAddress((void**)&A0l, g_A0l);
    cudaGetSymbolAddress((void**)&A1h, g_A1h);
    cudaGetSymbolAddress((void**)&A1l, g_A1l);
    cudaGetSymbolAddress((void**)&Wh,  g_Wh);
    cudaGetSymbolAddress((void**)&Wl,  g_Wl);
    cudaGetSymbolAddress((void**)&Qh,  g_Qh);
    cudaGetSymbolAddress((void**)&Ql,  g_Ql);
    cudaGetSymbolAddress((void**)&Kh,  g_Kh);
    cudaGetSymbolAddress((void**)&Kl,  g_Kl);
    cudaGetSymbolAddress((void**)&Vh,  g_Vh);
    cudaGetSymbolAddress((void**)&Vl,  g_Vl);

    cudaFuncSetAttribute(attn_mma, cudaFuncAttributeMaxDynamicSharedMemorySize, ATTN_SMEM);
    cudaFuncSetAttribute(mma_gemm<0, 0>, cudaFuncAttributeMaxDynamicSharedMemorySize, GEMM_SMEM);
    cudaFuncSetAttribute(mma_gemm<0, 2>, cudaFuncAttributeMaxDynamicSharedMemorySize, GEMM_SMEM);
    cudaFuncSetAttribute(mma_gemm<1, 1>, cudaFuncAttributeMaxDynamicSharedMemorySize, GEMM_SMEM);
    cudaFuncSetAttribute(mma_gemm<2, 0>, cudaFuncAttributeMaxDynamicSharedMemorySize, GEMM_SMEM);
    cudaFuncSetAttribute(mma_gemm<3, 0>, cudaFuncAttributeMaxDynamicSharedMemorySize, GEMM_SMEM);

    // 0. fused prep: all weights hilo + x hilo + rope table
    prep_kernel<<<14528, 256>>>(x, qp, kp, wv, wproj, ew0, ew1, ew2, ewout,
                                Wh, Wl, A0h, A0l, rope);
    // 1. QKV GEMM with fused RoPE epilogue -> Q/K/V hilo directly
    mma_gemm<0, 2><<<dim3(8, 32), 256, GEMM_SMEM>>>(A0h, A0l, Wh, Wl, nullptr, nullptr,
                                                    1024, 1024, nullptr, Vh, Vl,
                                                    Qh, Ql, Kh, Kl, rope, qg);
    // 2. HMMA flash attention -> A1 hilo
    attn_mma<<<dim3(16, 8, 2), 256, ATTN_SMEM>>>(Qh, Ql, Kh, Kl, Vh, Vl, A1h, A1l);
    // 3. h = x + y @ wproj^T  (+ hilo(h) -> A0)
    mma_gemm<1, 1><<<dim3(4, 32), 256, GEMM_SMEM>>>(A1h, A1l, Wh + 1024 * 512, Wl + 1024 * 512,
                                                    x, hb, 512, 512, nullptr, A0h, A0l,
                                                    nullptr, nullptr, nullptr, nullptr, nullptr, nullptr);
    // 4. t1 = h @ ew0^T
    mma_gemm<0, 0><<<dim3(4, 32), 256, GEMM_SMEM>>>(A0h, A0l, Wh + 1536 * 512, Wl + 1536 * 512,
                                                    nullptr, t1, 512, 512, nullptr, nullptr, nullptr,
                                                    nullptr, nullptr, nullptr, nullptr, nullptr, nullptr);
    ln_hilo<<<512, 256>>>(t1, g1, b1, A1h, A1l);
    // 5. t3 = h + silu(ln1 @ ew1^T)
    mma_gemm<2, 0><<<dim3(4, 32), 256, GEMM_SMEM>>>(A1h, A1l, Wh + 2048 * 512, Wl + 2048 * 512,
                                                    hb, t3, 512, 512, nullptr, nullptr, nullptr,
                                                    nullptr, nullptr, nullptr, nullptr, nullptr, nullptr);
    ln_hilo<<<512, 256>>>(t3, g2, b2, A0h, A0l);
    // 6. t2 = t3 + silu(ln2 @ ew2^T)
    mma_gemm<2, 0><<<dim3(4, 32), 256, GEMM_SMEM>>>(A0h, A0l, Wh + 2560 * 512, Wl + 2560 * 512,
                                                    t3, t2, 512, 512, nullptr, nullptr, nullptr,
                                                    nullptr, nullptr, nullptr, nullptr, nullptr, nullptr);
    // 7. rms + head
    rms_hilo<<<512, 256>>>(t2, A1h, A1l);
    mma_gemm<3, 0><<<dim3(1, 32), 256, GEMM_SMEM>>>(A1h, A1l, Wh + 3072 * 512, Wl + 3072 * 512,
                                                    nullptr, out, 32, 32, ctemp, nullptr, nullptr,
                                                    nullptr, nullptr, nullptr, nullptr, nullptr, nullptr);
}

// round 16
// speedup vs baseline: 1.0271x; 1.0271x over previous
#include <cuda_runtime.h>
#include <cuda_bf16.h>
#include <math.h>
#include <math_constants.h>
#include <cstdint>

#define T_LEN 2048

// ---------------- scratch (no allocations allowed) ----------------
__device__ float g_h [4096 * 512];
__device__ float g_t1[4096 * 512];
__device__ float g_t2[4096 * 512];
__device__ float g_t3[4096 * 512];
__device__ float g_rope[2048 * 16 * 2];
__device__ __nv_bfloat16 g_A0h[4096 * 512], g_A0l[4096 * 512];
__device__ __nv_bfloat16 g_A1h[4096 * 512], g_A1l[4096 * 512];
__device__ __nv_bfloat16 g_Qh[4096 * 256], g_Ql[4096 * 256];
__device__ __nv_bfloat16 g_Kh[4096 * 256], g_Kl[4096 * 256];
__device__ __nv_bfloat16 g_Vh[4096 * 512], g_Vl[4096 * 512];
// weight rows: [0:1024) qkv | [1024:1536) wproj | [1536:2048) ew0 | [2048:2560) ew1 | [2560:3072) ew2 | [3072:3104) ewout
__device__ __nv_bfloat16 g_Wh[3104 * 512], g_Wl[3104 * 512];

// ---------------- helpers ----------------
static __device__ __forceinline__ uint32_t smem_u32(const void* p) {
    uint32_t a;
    asm("{ .reg .u64 t; cvta.to.shared.u64 t, %1; cvt.u32.u64 %0, t; }" : "=r"(a) : "l"(p));
    return a;
}
static __device__ __forceinline__ void hilo(float v, __nv_bfloat16& h, __nv_bfloat16& l) {
    h = __float2bfloat16(v);
    l = __float2bfloat16(v - __bfloat162float(h));
}
static __device__ __forceinline__ void packhl(float a, float b, uint32_t& ph, uint32_t& pl) {
    __nv_bfloat162 hp, lp;
    hp.x = __float2bfloat16(a);
    hp.y = __float2bfloat16(b);
    lp.x = __float2bfloat16(a - __bfloat162float(hp.x));
    lp.y = __float2bfloat16(b - __bfloat162float(hp.y));
    ph = *(uint32_t*)&hp;
    pl = *(uint32_t*)&lp;
}

#define LDSM_X4(r, a)                                                          \
    asm volatile("ldmatrix.sync.aligned.m8n8.x4.shared.b16 {%0,%1,%2,%3}, [%4];" \
        : "=r"((r)[0]), "=r"((r)[1]), "=r"((r)[2]), "=r"((r)[3]) : "r"(a))
#define LDSM_X2(r, a)                                                          \
    asm volatile("ldmatrix.sync.aligned.m8n8.x2.shared.b16 {%0,%1}, [%2];"     \
        : "=r"((r)[0]), "=r"((r)[1]) : "r"(a))
#define LDSM_X4_T(r, a)                                                        \
    asm volatile("ldmatrix.sync.aligned.m8n8.x4.trans.shared.b16 {%0,%1,%2,%3}, [%4];" \
        : "=r"((r)[0]), "=r"((r)[1]), "=r"((r)[2]), "=r"((r)[3]) : "r"(a))
#define MMA_BF16(d, A, B)                                                      \
    asm volatile("mma.sync.aligned.m16n8k16.row.col.f32.bf16.bf16.f32 "        \
        "{%0,%1,%2,%3}, {%4,%5,%6,%7}, {%8,%9}, {%0,%1,%2,%3};"                \
        : "+f"((d)[0]), "+f"((d)[1]), "+f"((d)[2]), "+f"((d)[3])               \
        : "r"((A)[0]), "r"((A)[1]), "r"((A)[2]), "r"((A)[3]),                  \
          "r"((B)[0]), "r"((B)[1]))
#define CPA(dst, src, sz) \
    asm volatile("cp.async.ca.shared.global [%0], [%1], 16, %2;" :: "r"(dst), "l"(src), "r"(sz))
#define CP_COMMIT asm volatile("cp.async.commit_group;" ::: "memory")
#define CP_WAIT0  asm volatile("cp.async.wait_group 0;" ::: "memory")
#define CP_WAIT1  asm volatile("cp.async.wait_group 1;" ::: "memory")

// ---------------- fused prep: weights hilo + x hilo + rope table ----------------
__global__ void prep_kernel(
    const float* __restrict__ x, const float* __restrict__ qp, const float* __restrict__ kp,
    const float* __restrict__ wv, const float* __restrict__ wproj,
    const float* __restrict__ ew0, const float* __restrict__ ew1,
    const float* __restrict__ ew2, const float* __restrict__ ewout,
    __nv_bfloat16* __restrict__ Wh, __nv_bfloat16* __restrict__ Wl,
    __nv_bfloat16* __restrict__ A0h, __nv_bfloat16* __restrict__ A0l,
    float* __restrict__ rope)
{
    int idx = blockIdx.x * blockDim.x + threadIdx.x;
    if (idx < 524288) {
        int n = idx >> 9, d = idx & 511;
        float v;
        if (n < 256) v = qp[((n >> 5) * 512 + d) * 32 + (n & 31)];
        else if (n < 512) { int nn = n - 256; v = kp[((nn >> 5) * 512 + d) * 32 + (nn & 31)]; }
        else v = wv[(size_t)(n - 512) * 512 + d];
        hilo(v, Wh[idx], Wl[idx]);
    } else if (idx < 786432) {
        int i = idx - 524288;
        hilo(wproj[i], Wh[1024 * 512 + i], Wl[1024 * 512 + i]);
    } else if (idx < 1048576) {
        int i = idx - 786432;
        hilo(ew0[i], Wh[1536 * 512 + i], Wl[1536 * 512 + i]);
    } else if (idx < 1310720) {
        int i = idx - 1048576;
        hilo(ew1[i], Wh[2048 * 512 + i], Wl[2048 * 512 + i]);
    } else if (idx < 1572864) {
        int i = idx - 1310720;
        hilo(ew2[i], Wh[2560 * 512 + i], Wl[2560 * 512 + i]);
    } else if (idx < 1589248) {
        int i = idx - 1572864;
        hilo(ewout[i], Wh[3072 * 512 + i], Wl[3072 * 512 + i]);
    } else if (idx < 3686400) {
        int i = idx - 1589248;
        hilo(x[i], A0h[i], A0l[i]);
    } else if (idx < 3719168) {
        int i2 = idx - 3686400;       // t*16 + i
        int t = i2 >> 4, i = i2 & 15;
        double fd = pow(10000.0, -(double)(2 * i) / 32.0);
        float ang = (float)t * (float)fd;
        double ad = (double)ang;
        rope[i2 * 2]     = (float)cos(ad);
        rope[i2 * 2 + 1] = (float)sin(ad);
    }
}

// ---------------- HMMA bf16x3 GEMM, tile 128x128, 512 threads (16 warps, 4m x 4n) ----------------
// D[m][n] = sum_k A[m][k]*B[n][k], K=512. Warp tile 32x32.
// EPI: 0 none, 1 res+acc, 2 res+silu(acc), 3 tanh(acc/(softplus(extra[n])+1e-4))
// OMODE: 0 none, 1 full hilo out, 2 QKV fused epilogue (rope for n<512, V hilo for n>=512)
#define PAD 72
#define ARR (128 * PAD)
#define STAGEB (4 * ARR * 2)
#define GEMM_SMEM (2 * STAGEB)
template <int EPI, int OMODE>
__global__ void __launch_bounds__(512, 1) mma_gemm(
    const __nv_bfloat16* __restrict__ Ah, const __nv_bfloat16* __restrict__ Al,
    const __nv_bfloat16* __restrict__ Bh, const __nv_bfloat16* __restrict__ Bl,
    const float* __restrict__ Res, float* __restrict__ C,
    int Ntot, int NtotB, const float* __restrict__ extra,
    __nv_bfloat16* __restrict__ Oh, __nv_bfloat16* __restrict__ Ol,
    __nv_bfloat16* __restrict__ Qh, __nv_bfloat16* __restrict__ Ql,
    __nv_bfloat16* __restrict__ Kh, __nv_bfloat16* __restrict__ Kl,
    const float* __restrict__ rope_tab, const float* __restrict__ qgain)
{
    extern __shared__ __nv_bfloat16 smb[];
    uint32_t sbase = smem_u32(smb);

    int tid = threadIdx.x, lane = tid & 31, wid = tid >> 5;
    int warp_m = wid & 3, warp_n = wid >> 2;        // 4 x 4 warps
    int m0 = blockIdx.y * 128, n0 = blockIdx.x * 128;

    uint32_t a_row = warp_m * 32 + (lane & 15);
    uint32_t a_ko  = (lane >> 4) * 8;
    uint32_t b_row = warp_n * 32 + (lane & 7);
    uint32_t b_ko  = ((lane >> 3) & 1) * 8;

    float acc[2][4][4] = {};

    auto issue = [&](int c) {
        uint32_t st = (uint32_t)(c & 1) * STAGEB;
        int k0c = c * 64;
#pragma unroll
        for (int t = 0; t < 2; t++) {
            int idx = tid + t * 512;
            int r = idx >> 3, q = idx & 7;
            uint32_t so = st + (uint32_t)(r * PAD + q * 8) * 2;
            size_t g = (size_t)(m0 + r) * 512 + k0c + q * 8;
            CPA(sbase + so,            Ah + g, 16);
            CPA(sbase + so + ARR * 2,  Al + g, 16);
        }
#pragma unroll
        for (int t = 0; t < 2; t++) {
            int idx = tid + t * 512;
            int r = idx >> 3, q = idx & 7;
            uint32_t so = st + (uint32_t)(2 * ARR + r * PAD + q * 8) * 2;
            int n = n0 + r;
            int ok = (n < NtotB) ? 16 : 0;
            size_t g = (size_t)(ok ? n : 0) * 512 + k0c + q * 8;
            CPA(sbase + so,            Bh + g, ok);
            CPA(sbase + so + ARR * 2,  Bl + g, ok);
        }
        CP_COMMIT;
    };

    issue(0);
    for (int c = 0; c < 8; c++) {
        CP_WAIT0;
        __syncthreads();
        if (c < 7) issue(c + 1);

        uint32_t st = (uint32_t)(c & 1) * STAGEB;
        uint32_t uAh = sbase + st;
        uint32_t uAl = uAh + ARR * 2;
        uint32_t uBh = uAl + ARR * 2;
        uint32_t uBl = uBh + ARR * 2;

#pragma unroll
        for (int kk = 0; kk < 4; kk++) {
            uint32_t bh[4][2], bl[4][2];
#pragma unroll
            for (int ni = 0; ni < 4; ni++) {
                uint32_t off = ((b_row + ni * 8) * PAD + kk * 16 + b_ko) * 2;
                LDSM_X2(bh[ni], uBh + off);
                LDSM_X2(bl[ni], uBl + off);
            }
            uint32_t ah[2][4], al[2][4];
#pragma unroll
            for (int mi = 0; mi < 2; mi++) {
                uint32_t off = ((a_row + mi * 16) * PAD + kk * 16 + a_ko) * 2;
                LDSM_X4(ah[mi], uAh + off);
                LDSM_X4(al[mi], uAl + off);
            }
            // term-major: consecutive MMAs hit different accumulators
#pragma unroll
            for (int mi = 0; mi < 2; mi++)
#pragma unroll
                for (int ni = 0; ni < 4; ni++)
                    MMA_BF16(acc[mi][ni], ah[mi], bh[ni]);
#pragma unroll
            for (int mi = 0; mi < 2; mi++)
#pragma unroll
                for (int ni = 0; ni < 4; ni++)
                    MMA_BF16(acc[mi][ni], ah[mi], bl[ni]);
#pragma unroll
            for (int mi = 0; mi < 2; mi++)
#pragma unroll
                for (int ni = 0; ni < 4; ni++)
                    MMA_BF16(acc[mi][ni], al[mi], bh[ni]);
        }
        __syncthreads();
    }

    // epilogue
    int gid = lane >> 2, tig = lane & 3;

    if (OMODE == 2) {
        int colbase = n0 + warp_n * 32;   // warp-uniform, one 32-col head group
        if (colbase < 512) {
            // q/k region: rope rotate in-register, pairs (ni, ni+2)
            int which = colbase >= 256;
            int hh = (colbase >> 5) & 7;
            float scale = which ? 1.0f : (qgain[hh] * 0.17677669529663687f);
            __nv_bfloat16* dh = which ? Kh : Qh;
            __nv_bfloat16* dl = which ? Kl : Ql;
            int off0 = colbase & 255;
#pragma unroll
            for (int mi = 0; mi < 2; mi++) {
#pragma unroll
                for (int half = 0; half < 2; half++) {
                    int m = m0 + warp_m * 32 + mi * 16 + gid + half * 8;
                    int t = m & (T_LEN - 1);
#pragma unroll
                    for (int ni = 0; ni < 2; ni++) {
#pragma unroll
                        for (int e = 0; e < 2; e++) {
                            int i = ni * 8 + tig * 2 + e;
                            float x1 = acc[mi][ni][half * 2 + e];
                            float x2 = acc[mi][ni + 2][half * 2 + e];
                            float cth = rope_tab[(t * 16 + i) * 2];
                            float sth = rope_tab[(t * 16 + i) * 2 + 1];
                            float o1 = (x1 * cth - x2 * sth) * scale;
                            float o2 = (x2 * cth + x1 * sth) * scale;
                            __nv_bfloat16 h1, l1, h2, l2;
                            hilo(o1, h1, l1); hilo(o2, h2, l2);
                            size_t base = (size_t)m * 256 + off0 + i;
                            dh[base] = h1;      dl[base] = l1;
                            dh[base + 16] = h2; dl[base + 16] = l2;
                        }
                    }
                }
            }
        } else {
            // V region: hilo split
#pragma unroll
            for (int mi = 0; mi < 2; mi++) {
#pragma unroll
                for (int ni = 0; ni < 4; ni++) {
#pragma unroll
                    for (int half = 0; half < 2; half++) {
                        int m = m0 + warp_m * 32 + mi * 16 + gid + half * 8;
                        int nb = colbase + ni * 8 + tig * 2;
#pragma unroll
                        for (int e = 0; e < 2; e++) {
                            int n = nb + e;
                            __nv_bfloat16 hx, lx;
                            hilo(acc[mi][ni][half * 2 + e], hx, lx);
                            Oh[(size_t)m * 512 + (n - 512)] = hx;
                            Ol[(size_t)m * 512 + (n - 512)] = lx;
                        }
                    }
                }
            }
        }
        return;
    }

#pragma unroll
    for (int mi = 0; mi < 2; mi++) {
#pragma unroll
        for (int ni = 0; ni < 4; ni++) {
#pragma unroll
            for (int half = 0; half < 2; half++) {
                int m = m0 + warp_m * 32 + mi * 16 + gid + half * 8;
                int nbase = n0 + warp_n * 32 + ni * 8 + tig * 2;
#pragma unroll
                for (int e = 0; e < 2; e++) {
                    int n = nbase + e;
                    if (n >= Ntot) continue;
                    float v = acc[mi][ni][half * 2 + e];
                    if (EPI == 1) {
                        v += Res[(size_t)m * Ntot + n];
                    } else if (EPI == 2) {
                        float sg = 1.0f / (1.0f + __expf(-v));
                        v = Res[(size_t)m * Ntot + n] + v * sg;
                    } else if (EPI == 3) {
                        float ct = extra[n];
                        float sp = (ct > 20.0f) ? ct : log1pf(__expf(ct));
                        v = tanhf(v / (sp + 1e-4f));
                    }
                    C[(size_t)m * Ntot + n] = v;
                    if (OMODE == 1) {
                        __nv_bfloat16 hx, lx;
                        hilo(v, hx, lx);
                        Oh[(size_t)m * 512 + n] = hx;
                        Ol[(size_t)m * 512 + n] = lx;
                    }
                }
            }
        }
    }
}

// ---------------- HMMA flash attention + self-align, bf16x3, cp.async double-buffered ----------------
// BQ=128 (8 warps), K tiles of 64, 2-stage K/V pipeline. grid (16, 8, 2), 256 thr.
#define AQ_E   (128 * 40)
#define AK_E   (64 * 40)
#define AV_E   (64 * 72)
#define ASTAGE (2 * AK_E + 2 * AV_E)
#define ATTN_SMEM ((2 * AQ_E + 2 * ASTAGE) * 2)   // 77824 bytes
__global__ void __launch_bounds__(256, 2) attn_mma(
    const __nv_bfloat16* __restrict__ Qh_, const __nv_bfloat16* __restrict__ Ql_,
    const __nv_bfloat16* __restrict__ Kh_, const __nv_bfloat16* __restrict__ Kl_,
    const __nv_bfloat16* __restrict__ Vh_, const __nv_bfloat16* __restrict__ Vl_,
    __nv_bfloat16* __restrict__ yh, __nv_bfloat16* __restrict__ yl)
{
    extern __shared__ __nv_bfloat16 sb[];
    __nv_bfloat16* sQh = sb;
    __nv_bfloat16* sQl = sQh + AQ_E;
    __nv_bfloat16* stage0 = sQl + AQ_E;

    int qb = (int)gridDim.x - 1 - (int)blockIdx.x;
    int h = blockIdx.y, b = blockIdx.z;
    int tid = threadIdx.x, lane = tid & 31, w = tid >> 5;
    int q0 = qb * 128;
    int rw = q0 + w * 16;
    const size_t hb = (size_t)b * T_LEN;
    int ntiles = 2 * qb + 2;

    auto issueKV = [&](int j) {
        int k0 = j * 64;
        uint32_t st = smem_u32(stage0 + (j & 1) * ASTAGE);
        {
            int r = tid >> 2, seg = tid & 3;
            size_t g = (hb + k0 + r) * 256 + h * 32 + seg * 8;
            uint32_t d = st + (uint32_t)(r * 40 + seg * 8) * 2;
            CPA(d,              Kh_ + g, 16);
            CPA(d + AK_E * 2,   Kl_ + g, 16);
        }
#pragma unroll
        for (int t2 = 0; t2 < 2; t2++) {
            int idx = tid + t2 * 256;
            int r = idx >> 3, seg = idx & 7;
            size_t g = (hb + k0 + r) * 512 + h * 64 + seg * 8;
            uint32_t d = st + (uint32_t)(2 * AK_E + r * 72 + seg * 8) * 2;
            CPA(d,              Vh_ + g, 16);
            CPA(d + AV_E * 2,   Vl_ + g, 16);
        }
        CP_COMMIT;
    };

    issueKV(0);

    for (int i = tid; i < 512; i += 256) {
        int r = i >> 2, seg = i & 3;
        size_t g = (hb + q0 + r) * 256 + h * 32 + seg * 8;
        *(float4*)(sQh + r * 40 + seg * 8) = *(const float4*)(Qh_ + g);
        *(float4*)(sQl + r * 40 + seg * 8) = *(const float4*)(Ql_ + g);
    }
    __syncthreads();

    uint32_t qfh[2][4], qfl[2][4];
    {
        int mrow = (lane & 7) + 8 * ((lane >> 3) & 1);
        int koff = 8 * (lane >> 4);
#pragma unroll
        for (int kj = 0; kj < 2; kj++) {
            LDSM_X4(qfh[kj], smem_u32(sQh + (w * 16 + mrow) * 40 + kj * 16 + koff));
            LDSM_X4(qfl[kj], smem_u32(sQl + (w * 16 + mrow) * 40 + kj * 16 + koff));
        }
    }

    float m_[2] = {-1e30f, -1e30f}, l_[2] = {0.f, 0.f};
    float o[8][4] = {};

    for (int j = 0; j < ntiles; j++) {
        if (j > 0) __syncthreads();
        if (j + 1 < ntiles) { issueKV(j + 1); CP_WAIT1; }
        else                { CP_WAIT0; }
        __syncthreads();

        __nv_bfloat16* sKh = stage0 + (j & 1) * ASTAGE;
        __nv_bfloat16* sKl = sKh + AK_E;
        __nv_bfloat16* sVh = sKl + AK_E;
        __nv_bfloat16* sVl = sVh + AV_E;
        int k0 = j * 64;

        float s[8][4] = {};
        {
            int nrow = (lane & 7) + 8 * (lane >> 4);
            int koff = 8 * ((lane >> 3) & 1);
#pragma unroll
            for (int kj = 0; kj < 2; kj++) {
#pragma unroll
                for (int p = 0; p < 4; p++) {
                    uint32_t kb_h[4], kb_l[4];
                    LDSM_X4(kb_h, smem_u32(sKh + (p * 16 + nrow) * 40 + kj * 16 + koff));
                    LDSM_X4(kb_l, smem_u32(sKl + (p * 16 + nrow) * 40 + kj * 16 + koff));
                    MMA_BF16(s[2 * p],     qfh[kj], kb_h);
                    MMA_BF16(s[2 * p + 1], qfh[kj], kb_h + 2);
                    MMA_BF16(s[2 * p],     qfh[kj], kb_l);
                    MMA_BF16(s[2 * p + 1], qfh[kj], kb_l + 2);
                    MMA_BF16(s[2 * p],     qfl[kj], kb_h);
                    MMA_BF16(s[2 * p + 1], qfl[kj], kb_h + 2);
                }
            }
        }

        if (k0 + 63 > rw) {
#pragma unroll
            for (int nt = 0; nt < 8; nt++)
#pragma unroll
                for (int e = 0; e < 4; e++) {
                    int col = k0 + nt * 8 + (lane & 3) * 2 + (e & 1);
                    int row = rw + (lane >> 2) + (e >> 1) * 8;
                    if (col > row) s[nt][e] = -1e30f;
                }
        }

        float alpha[2];
#pragma unroll
        for (int half = 0; half < 2; half++) {
            float mx = -1e30f;
#pragma unroll
            for (int nt = 0; nt < 8; nt++)
                mx = fmaxf(mx, fmaxf(s[nt][2 * half], s[nt][2 * half + 1]));
            mx = fmaxf(mx, __shfl_xor_sync(0xffffffffu, mx, 1));
            mx = fmaxf(mx, __shfl_xor_sync(0xffffffffu, mx, 2));
            float mnew = fmaxf(m_[half], mx);
            alpha[half] = __expf(m_[half] - mnew);
            m_[half] = mnew;
            float sum = 0.f;
#pragma unroll
            for (int nt = 0; nt < 8; nt++) {
                s[nt][2 * half]     = __expf(s[nt][2 * half] - mnew);
                s[nt][2 * half + 1] = __expf(s[nt][2 * half + 1] - mnew);
                sum += s[nt][2 * half] + s[nt][2 * half + 1];
            }
            sum += __shfl_xor_sync(0xffffffffu, sum, 1);
            sum += __shfl_xor_sync(0xffffffffu, sum, 2);
            l_[half] = l_[half] * alpha[half] + sum;
        }
#pragma unroll
        for (int dt = 0; dt < 8; dt++) {
            o[dt][0] *= alpha[0]; o[dt][1] *= alpha[0];
            o[dt][2] *= alpha[1]; o[dt][3] *= alpha[1];
        }

        uint32_t pah[4][4], pal[4][4];
#pragma unroll
        for (int kj = 0; kj < 4; kj++) {
            packhl(s[2 * kj][0],     s[2 * kj][1],     pah[kj][0], pal[kj][0]);
            packhl(s[2 * kj][2],     s[2 * kj][3],     pah[kj][1], pal[kj][1]);
            packhl(s[2 * kj + 1][0], s[2 * kj + 1][1], pah[kj][2], pal[kj][2]);
            packhl(s[2 * kj + 1][2], s[2 * kj + 1][3], pah[kj][3], pal[kj][3]);
        }

        {
            int vrow = lane & 15;
            int vcol = 8 * (lane >> 4);
#pragma unroll
            for (int kj = 0; kj < 4; kj++) {
#pragma unroll
                for (int p = 0; p < 4; p++) {
                    uint32_t vb_h[4], vb_l[4];
                    LDSM_X4_T(vb_h, smem_u32(sVh + (kj * 16 + vrow) * 72 + p * 16 + vcol));
                    LDSM_X4_T(vb_l, smem_u32(sVl + (kj * 16 + vrow) * 72 + p * 16 + vcol));
                    MMA_BF16(o[2 * p],     pah[kj], vb_h);
                    MMA_BF16(o[2 * p + 1], pah[kj], vb_h + 2);
                    MMA_BF16(o[2 * p],     pah[kj], vb_l);
                    MMA_BF16(o[2 * p + 1], pah[kj], vb_l + 2);
                    MMA_BF16(o[2 * p],     pal[kj], vb_h);
                    MMA_BF16(o[2 * p + 1], pal[kj], vb_h + 2);
                }
            }
        }
    }

#pragma unroll
    for (int half = 0; half < 2; half++) {
        int row = rw + (lane >> 2) + half * 8;
        float dp = 0.f, nn = 0.f;
        float vv[8][2];
#pragma unroll
        for (int dt = 0; dt < 8; dt++) {
            int c0 = dt * 8 + (lane & 3) * 2;
            size_t g = (hb + row) * 512 + h * 64 + c0;
            __nv_bfloat162 th = *(const __nv_bfloat162*)(Vh_ + g);
            __nv_bfloat162 tl = *(const __nv_bfloat162*)(Vl_ + g);
            float v0 = __bfloat162float(th.x) + __bfloat162float(tl.x);
            float v1 = __bfloat162float(th.y) + __bfloat162float(tl.y);
            vv[dt][0] = v0; vv[dt][1] = v1;
            dp += o[dt][2 * half] * v0 + o[dt][2 * half + 1] * v1;
            nn += v0 * v0 + v1 * v1;
        }
        dp += __shfl_xor_sync(0xffffffffu, dp, 1);
        dp += __shfl_xor_sync(0xffffffffu, dp, 2);
        nn += __shfl_xor_sync(0xffffffffu, nn, 1);
        nn += __shfl_xor_sync(0xffffffffu, nn, 2);
        float coef = dp / fmaxf(nn, 1e-24f);
        float linv = 1.0f / l_[half];
#pragma unroll
        for (int dt = 0; dt < 8; dt++) {
            int c0 = dt * 8 + (lane & 3) * 2;
            size_t g = (hb + row) * 512 + h * 64 + c0;
            float y0 = (o[dt][2 * half]     - coef * vv[dt][0]) * linv;
            float y1 = (o[dt][2 * half + 1] - coef * vv[dt][1]) * linv;
            uint32_t ph, pl;
            packhl(y0, y1, ph, pl);
            *(uint32_t*)(yh + g) = ph;
            *(uint32_t*)(yl + g) = pl;
        }
    }
}

// ---------------- layernorm -> bf16 hi/lo ----------------
__global__ void ln_hilo(const float* __restrict__ in, const float* __restrict__ g,
                        const float* __restrict__ bta,
                        __nv_bfloat16* __restrict__ oh, __nv_bfloat16* __restrict__ ol) {
    int row = blockIdx.x * 8 + (threadIdx.x >> 5);
    int lane = threadIdx.x & 31;
    const float* p = in + (size_t)row * 512;
    float v[16];
    float s = 0.f;
#pragma unroll
    for (int j = 0; j < 16; j++) { v[j] = p[lane + 32 * j]; s += v[j]; }
#pragma unroll
    for (int off = 16; off; off >>= 1) s += __shfl_xor_sync(0xffffffffu, s, off);
    float mean = s * (1.0f / 512.0f);
    float s2 = 0.f;
#pragma unroll
    for (int j = 0; j < 16; j++) { float d = v[j] - mean; s2 += d * d; }
#pragma unroll
    for (int off = 16; off; off >>= 1) s2 += __shfl_xor_sync(0xffffffffu, s2, off);
    float r = rsqrtf(s2 * (1.0f / 512.0f) + 1e-5f);
#pragma unroll
    for (int j = 0; j < 16; j++) {
        int c = lane + 32 * j;
        float ov = (v[j] - mean) * r * g[c] + bta[c];
        __nv_bfloat16 hx, lx;
        hilo(ov, hx, lx);
        oh[(size_t)row * 512 + c] = hx;
        ol[(size_t)row * 512 + c] = lx;
    }
}

// ---------------- RMS norm -> bf16 hi/lo ----------------
__global__ void rms_hilo(const float* __restrict__ in,
                         __nv_bfloat16* __restrict__ oh, __nv_bfloat16* __restrict__ ol) {
    int row = blockIdx.x * 8 + (threadIdx.x >> 5);
    int lane = threadIdx.x & 31;
    const float* p = in + (size_t)row * 512;
    float v[16];
    float s2 = 0.f;
#pragma unroll
    for (int j = 0; j < 16; j++) { v[j] = p[lane + 32 * j]; s2 += v[j] * v[j]; }
#pragma unroll
    for (int off = 16; off; off >>= 1) s2 += __shfl_xor_sync(0xffffffffu, s2, off);
    float r = rsqrtf(s2 * (1.0f / 512.0f) + 1e-6f);
#pragma unroll
    for (int j = 0; j < 16; j++) {
        float ov = v[j] * r;
        __nv_bfloat16 hx, lx;
        hilo(ov, hx, lx);
        oh[(size_t)row * 512 + lane + 32 * j] = hx;
        ol[(size_t)row * 512 + lane + 32 * j] = lx;
    }
}

// ---------------- launch ----------------
extern "C" void kernel_launch(void* const* d_in, const int* in_sizes, int n_in,
                              void* d_out, int out_size) {
    const float* x      = (const float*)d_in[0];
    const float* qp     = (const float*)d_in[1];
    const float* kp     = (const float*)d_in[2];
    const float* wv     = (const float*)d_in[3];
    const float* wproj  = (const float*)d_in[4];
    const float* qg     = (const float*)d_in[5];
    const float* ew0    = (const float*)d_in[6];
    const float* g1     = (const float*)d_in[7];
    const float* b1     = (const float*)d_in[8];
    const float* ew1    = (const float*)d_in[9];
    const float* g2     = (const float*)d_in[10];
    const float* b2     = (const float*)d_in[11];
    const float* ew2    = (const float*)d_in[12];
    const float* ewout  = (const float*)d_in[13];
    const float* ctemp  = (const float*)d_in[14];
    float* out = (float*)d_out;

    float *hb, *t1, *t2, *t3, *rope;
    __nv_bfloat16 *A0h, *A0l, *A1h, *A1l, *Wh, *Wl, *Qh, *Ql, *Kh, *Kl, *Vh, *Vl;
    cudaGetSymbolAddress((void**)&hb,  g_h);
    cudaGetSymbolAddress((void**)&t1,  g_t1);
    cudaGetSymbolAddress((void**)&t2,  g_t2);
    cudaGetSymbolAddress((void**)&t3,  g_t3);
    cudaGetSymbolAddress((void**)&rope, g_rope);
    cudaGetSymbolAddress((void**)&A0h, g_A0h);
    cudaGetSymbolAddress((void**)&A0l, g_A0l);
    cudaGetSymbolAddress((void**)&A1h, g_A1h);
    cudaGetSymbolAddress((void**)&A1l, g_A1l);
    cudaGetSymbolAddress((void**)&Wh,  g_Wh);
    cudaGetSymbolAddress((void**)&Wl,  g_Wl);
    cudaGetSymbolAddress((void**)&Qh,  g_Qh);
    cudaGetSymbolAddress((void**)&Ql,  g_Ql);
    cudaGetSymbolAddress((void**)&Kh,  g_Kh);
    cudaGetSymbolAddress((void**)&Kl,  g_Kl);
    cudaGetSymbolAddress((void**)&Vh,  g_Vh);
    cudaGetSymbolAddress((void**)&Vl,  g_Vl);

    cudaFuncSetAttribute(attn_mma, cudaFuncAttributeMaxDynamicSharedMemorySize, ATTN_SMEM);
    cudaFuncSetAttribute(mma_gemm<0, 0>, cudaFuncAttributeMaxDynamicSharedMemorySize, GEMM_SMEM);
    cudaFuncSetAttribute(mma_gemm<0, 2>, cudaFuncAttributeMaxDynamicSharedMemorySize, GEMM_SMEM);
    cudaFuncSetAttribute(mma_gemm<1, 1>, cudaFuncAttributeMaxDynamicSharedMemorySize, GEMM_SMEM);
    cudaFuncSetAttribute(mma_gemm<2, 0>, cudaFuncAttributeMaxDynamicSharedMemorySize, GEMM_SMEM);
    cudaFuncSetAttribute(mma_gemm<3, 0>, cudaFuncAttributeMaxDynamicSharedMemorySize, GEMM_SMEM);

    // 0. fused prep: all weights hilo + x hilo + rope table
    prep_kernel<<<14528, 256>>>(x, qp, kp, wv, wproj, ew0, ew1, ew2, ewout,
                                Wh, Wl, A0h, A0l, rope);
    // 1. QKV GEMM with fused RoPE epilogue -> Q/K/V hilo directly
    mma_gemm<0, 2><<<dim3(8, 32), 512, GEMM_SMEM>>>(A0h, A0l, Wh, Wl, nullptr, nullptr,
                                                    1024, 1024, nullptr, Vh, Vl,
                                                    Qh, Ql, Kh, Kl, rope, qg);
    // 2. HMMA flash attention -> A1 hilo
    attn_mma<<<dim3(16, 8, 2), 256, ATTN_SMEM>>>(Qh, Ql, Kh, Kl, Vh, Vl, A1h, A1l);
    // 3. h = x + y @ wproj^T  (+ hilo(h) -> A0)
    mma_gemm<1, 1><<<dim3(4, 32), 512, GEMM_SMEM>>>(A1h, A1l, Wh + 1024 * 512, Wl + 1024 * 512,
                                                    x, hb, 512, 512, nullptr, A0h, A0l,
                                                    nullptr, nullptr, nullptr, nullptr, nullptr, nullptr);
    // 4. t1 = h @ ew0^T
    mma_gemm<0, 0><<<dim3(4, 32), 512, GEMM_SMEM>>>(A0h, A0l, Wh + 1536 * 512, Wl + 1536 * 512,
                                                    nullptr, t1, 512, 512, nullptr, nullptr, nullptr,
                                                    nullptr, nullptr, nullptr, nullptr, nullptr, nullptr);
    ln_hilo<<<512, 256>>>(t1, g1, b1, A1h, A1l);
    // 5. t3 = h + silu(ln1 @ ew1^T)
    mma_gemm<2, 0><<<dim3(4, 32), 512, GEMM_SMEM>>>(A1h, A1l, Wh + 2048 * 512, Wl + 2048 * 512,
                                                    hb, t3, 512, 512, nullptr, nullptr, nullptr,
                                                    nullptr, nullptr, nullptr, nullptr, nullptr, nullptr);
    ln_hilo<<<512, 256>>>(t3, g2, b2, A0h, A0l);
    // 6. t2 = t3 + silu(ln2 @ ew2^T)
    mma_gemm<2, 0><<<dim3(4, 32), 512, GEMM_SMEM>>>(A0h, A0l, Wh + 2560 * 512, Wl + 2560 * 512,
                                                    t3, t2, 512, 512, nullptr, nullptr, nullptr,
                                                    nullptr, nullptr, nullptr, nullptr, nullptr, nullptr);
    // 7. rms + head
    rms_hilo<<<512, 256>>>(t2, A1h, A1l);
    mma_gemm<3, 0><<<dim3(1, 32), 512, GEMM_SMEM>>>(A1h, A1l, Wh + 3072 * 512, Wl + 3072 * 512,
                                                    nullptr, out, 32, 32, ctemp, nullptr, nullptr,
                                                    nullptr, nullptr, nullptr, nullptr, nullptr, nullptr);
}